// round 7
// baseline (speedup 1.0000x reference)
#include <cuda_runtime.h>
#include <cuda_fp16.h>
#include <cstdint>

// ============================================================================
// Problem constants
// ============================================================================
#define GM 4096
#define GN 4096
#define GK 4096

// Scratch: dequantized weight, TRANSPOSED to [N][K] fp16 (K-major), 32 MB
__device__ __align__(1024) __half g_wt[(size_t)GN * GK];
// Scratch: x converted f32 -> fp16, [M][K], 32 MB
__device__ __align__(1024) __half g_xh[(size_t)GM * GK];

// Input-order flag: 1 if d_in[0] is q_weight (all int32 in [0,16)), 0 if it's x.
__device__ int g_order;

// ============================================================================
// Helpers
// ============================================================================
__device__ __forceinline__ uint32_t smem_u32(const void* p) {
    uint32_t a;
    asm("{ .reg .u64 t; cvta.to.shared.u64 t, %1; cvt.u32.u64 %0, t; }" : "=r"(a) : "l"(p));
    return a;
}
#define SWZ(off) ((off) ^ (((off) >> 3) & 0x70))

__device__ __forceinline__ void cp_async16(uint32_t dst, const void* src) {
    asm volatile("cp.async.cg.shared.global [%0], [%1], 16;" :: "r"(dst), "l"(src));
}
#define CP_COMMIT() asm volatile("cp.async.commit_group;" ::: "memory")
#define CP_WAIT(n)  asm volatile("cp.async.wait_group %0;" :: "n"(n) : "memory")

__device__ __forceinline__ void ldmatrix_x4(uint32_t* r, uint32_t addr) {
    asm volatile("ldmatrix.sync.aligned.m8n8.x4.shared.b16 {%0,%1,%2,%3}, [%4];"
                 : "=r"(r[0]), "=r"(r[1]), "=r"(r[2]), "=r"(r[3]) : "r"(addr));
}

__device__ __forceinline__ void mma16816(float* c, const uint32_t* a, uint32_t b0, uint32_t b1) {
    asm volatile(
        "mma.sync.aligned.m16n8k16.row.col.f32.f16.f16.f32 "
        "{%0,%1,%2,%3}, {%4,%5,%6,%7}, {%8,%9}, {%0,%1,%2,%3};"
        : "+f"(c[0]), "+f"(c[1]), "+f"(c[2]), "+f"(c[3])
        : "r"(a[0]), "r"(a[1]), "r"(a[2]), "r"(a[3]), "r"(b0), "r"(b1));
}

// ============================================================================
// Pass 0: probe which input slot holds q_weight (int32 values all in [0,16)).
// ============================================================================
__global__ void probe_kernel(const int* __restrict__ p0) {
    if (threadIdx.x == 0) {
        int ok = 1;
        for (int i = 0; i < 4096; i++) {
            unsigned v = (unsigned)p0[i];
            if (v >= 16u) { ok = 0; break; }
        }
        g_order = ok;
    }
}

// ============================================================================
// Pass 0.5: convert x (float32) -> g_xh (fp16). 8 elems/thread, vectorized.
// ============================================================================
__global__ void __launch_bounds__(256) convert_x_kernel(const void* __restrict__ p0,
                                                        const void* __restrict__ p2) {
    const float* xf = g_order ? (const float*)p2 : (const float*)p0;
    const size_t i = ((size_t)blockIdx.x * 256 + threadIdx.x) * 8;
    const float4 v0 = *(const float4*)(xf + i);
    const float4 v1 = *(const float4*)(xf + i + 4);
    union { uint2 u; __half2 h[2]; } lo, hi;
    lo.h[0] = __floats2half2_rn(v0.x, v0.y);
    lo.h[1] = __floats2half2_rn(v0.z, v0.w);
    hi.h[0] = __floats2half2_rn(v1.x, v1.y);
    hi.h[1] = __floats2half2_rn(v1.z, v1.w);
    uint4 o;
    o.x = lo.u.x; o.y = lo.u.y; o.z = hi.u.x; o.w = hi.u.y;
    *(uint4*)(&g_xh[i]) = o;
}

// ============================================================================
// Pass 1: dequant + transpose (padded smem).
// g_wt[n][k] = (half)(q[k][n] - 8) * (half)scale[k/128][n]   (scale is f32)
// ============================================================================
__global__ void __launch_bounds__(256) dequant_kernel(const void* __restrict__ p0,
                                                      const void* __restrict__ p2,
                                                      const float* __restrict__ scale) {
    const int* q = g_order ? (const int*)p0 : (const int*)p2;

    __shared__ __align__(16) __half tw[64][80];  // [n][k], padded row = 160B
    __shared__ __half sc[64];
    const int t = threadIdx.x;
    const int n0 = blockIdx.x * 64;
    const int k0 = blockIdx.y * 64;

    if (t < 64) sc[t] = __float2half_rn(scale[(size_t)(k0 >> 7) * GN + n0 + t]);
    __syncthreads();

    const int kq = t >> 4;         // 0..15 -> k rows kq*4 .. kq*4+3
    const int nq = (t & 15) << 2;  // 0..60
    const int* gp = q + (size_t)(k0 + kq * 4) * GN + n0 + nq;
    int4 v[4];
#pragma unroll
    for (int j = 0; j < 4; j++) v[j] = *(const int4*)(gp + (size_t)j * GN);

#pragma unroll
    for (int jn = 0; jn < 4; jn++) {
        const int n = nq + jn;
        const __half s = sc[n];
#pragma unroll
        for (int j = 0; j < 4; j++) {
            const int a = ((const int*)&v[j])[jn];
            tw[n][kq * 4 + j] = __hmul(__int2half_rn(a - 8), s);
        }
    }
    __syncthreads();

#pragma unroll
    for (int i = 0; i < 2; i++) {
        const int idx = t + 256 * i;   // 0..511
        const int n = idx >> 3;        // 0..63
        const int c = idx & 7;         // 16B chunk (8 halfs)
        const uint4 val = *(const uint4*)&tw[n][c * 8];
        *(uint4*)(&g_wt[(size_t)(n0 + n) * GK + k0 + c * 8]) = val;
    }
}

// ============================================================================
// Pass 2: HMMA fp16 GEMM, f32 output (rounded through fp16).
// R7: CTA 256x128, 8 warps (4m x 2n), warp tile 64x64, 1 CTA/SM,
// double-buffered ldmatrix fragments (LDSM for ks+1 overlaps MMA for ks),
// single __syncthreads per k-tile, BK=64, 3-stage cp.async pipeline.
// ============================================================================
#define BM 256
#define BN 128
#define BK 64
#define STAGES 3
#define KTILES (GK / BK)  // 64

#define A_BYTES (BM * 128)                 // 32 KB
#define B_BYTES (BN * 128)                 // 16 KB
#define STAGE_BYTES (A_BYTES + B_BYTES)    // 48 KB
#define SMEM_TOTAL (1024 + STAGES * STAGE_BYTES)  // 148480 B -> 1 CTA/SM

// Epilogue staging: 256 rows x 512B padded to 528B = 135168 B <= SMEM_TOTAL
#define EP_STRIDE 528

__device__ __forceinline__ void load_tile(uint32_t sb, int s, int kt,
                                          int m0, int n0, int tid) {
    const uint32_t a0 = sb + s * STAGE_BYTES;
    const uint32_t b0 = a0 + A_BYTES;
    const char* ga = (const char*)(&g_xh[(size_t)m0 * GK + kt * BK]);
    const char* gb = (const char*)(&g_wt[(size_t)n0 * GK + kt * BK]);
#pragma unroll
    for (int i = 0; i < 8; i++) {  // A: 256 rows x 8 chunks = 2048 / 256 thr
        const int idx = tid + 256 * i;
        const int r = idx >> 3;
        const int c = (idx & 7) << 4;
        cp_async16(a0 + SWZ(r * 128 + c), ga + (size_t)r * (GK * 2) + c);
    }
#pragma unroll
    for (int i = 0; i < 4; i++) {  // B: 128 rows x 8 chunks = 1024 / 256 thr
        const int idx = tid + 256 * i;
        const int r = idx >> 3;
        const int c = (idx & 7) << 4;
        cp_async16(b0 + SWZ(r * 128 + c), gb + (size_t)r * (GK * 2) + c);
    }
}

__global__ void __launch_bounds__(256, 1)
gemm_kernel(float* __restrict__ out) {
    extern __shared__ unsigned char smem_raw[];

    const uint32_t sb_raw = smem_u32(smem_raw);
    const uint32_t sb = (sb_raw + 1023u) & ~1023u;  // 1KB-aligned tile base
    unsigned char* ep = smem_raw + (sb - sb_raw);   // same region, generic ptr

    const int tid = threadIdx.x;
    const int wid = tid >> 5;
    const int lid = tid & 31;
    const int m0 = blockIdx.x * BM;
    const int n0 = blockIdx.y * BN;

    const int wm = (wid & 3) * 64;   // warp m offset (4 m-rows of warps)
    const int wn = (wid >> 2) * 64;  // warp n offset (2 n-cols of warps)

    // acc[m-frag 0..3][n-frag 0..7][4] = 128 f32 regs
    float acc[4][8][4];
#pragma unroll
    for (int i = 0; i < 4; i++)
#pragma unroll
        for (int j = 0; j < 8; j++)
#pragma unroll
            for (int k = 0; k < 4; k++) acc[i][j][k] = 0.0f;

    // Prologue: fill first STAGES-1 stages
#pragma unroll
    for (int s = 0; s < STAGES - 1; s++) {
        load_tile(sb, s, s, m0, n0, tid);
        CP_COMMIT();
    }

    const int lrow = lid & 15;               // row within 16-row frag group
    const int lcol = ((lid >> 4) & 1) << 4;  // 0 or 16 bytes (k half-select)

    // Double-buffered fragments: a[buf][4 m-frags][4], b[buf][4 n16-groups][4]
    uint32_t afr[2][4][4], bfr[2][4][4];

    for (int kt = 0; kt < KTILES; kt++) {
        const int s = kt % STAGES;
        CP_WAIT(STAGES - 2);   // tile kt resident
        __syncthreads();       // all warps done reading stage (kt+2)%3 (used at kt-1)

        if (kt + STAGES - 1 < KTILES)
            load_tile(sb, (kt + STAGES - 1) % STAGES, kt + STAGES - 1, m0, n0, tid);
        CP_COMMIT();

        const uint32_t abase = sb + s * STAGE_BYTES;
        const uint32_t bbase = abase + A_BYTES;

        // Preload fragments for ks=0
#pragma unroll
        for (int f = 0; f < 4; f++) {
            ldmatrix_x4(afr[0][f], abase + SWZ((wm + f * 16 + lrow) * 128 + lcol));
            ldmatrix_x4(bfr[0][f], bbase + SWZ((wn + f * 16 + lrow) * 128 + lcol));
        }

#pragma unroll
        for (int ks = 0; ks < BK / 16; ks++) {
            const int cur = ks & 1;
            // Prefetch fragments for ks+1 (overlaps with this step's MMAs)
            if (ks < BK / 16 - 1) {
                const int kb = (ks + 1) * 32;
#pragma unroll
                for (int f = 0; f < 4; f++) {
                    ldmatrix_x4(afr[cur ^ 1][f], abase + SWZ((wm + f * 16 + lrow) * 128 + kb + lcol));
                    ldmatrix_x4(bfr[cur ^ 1][f], bbase + SWZ((wn + f * 16 + lrow) * 128 + kb + lcol));
                }
            }
#pragma unroll
            for (int im = 0; im < 4; im++)
#pragma unroll
                for (int in_ = 0; in_ < 4; in_++) {
                    mma16816(acc[im][in_ * 2 + 0], afr[cur][im], bfr[cur][in_][0], bfr[cur][in_][2]);
                    mma16816(acc[im][in_ * 2 + 1], afr[cur][im], bfr[cur][in_][1], bfr[cur][in_][3]);
                }
        }
    }

    __syncthreads();  // mainloop reads done before epilogue overwrites smem

    // ------------------------------------------------------------------
    // Epilogue: round f32 -> fp16 precision, stage in padded smem,
    // coalesced 16B f32 stores.
    // ------------------------------------------------------------------
#pragma unroll
    for (int im = 0; im < 4; im++) {
        const int r_lo = wm + im * 16 + (lid >> 2);
        const int r_hi = r_lo + 8;
#pragma unroll
        for (int nf = 0; nf < 8; nf++) {
            const int n = wn + nf * 8 + 2 * (lid & 3);  // even column index
            float2 lo, hi;
            lo.x = __half2float(__float2half_rn(acc[im][nf][0]));
            lo.y = __half2float(__float2half_rn(acc[im][nf][1]));
            hi.x = __half2float(__float2half_rn(acc[im][nf][2]));
            hi.y = __half2float(__float2half_rn(acc[im][nf][3]));
            *(float2*)(ep + r_lo * EP_STRIDE + n * 4) = lo;
            *(float2*)(ep + r_hi * EP_STRIDE + n * 4) = hi;
        }
    }
    __syncthreads();

#pragma unroll
    for (int i = 0; i < 32; i++) {
        const int idx = tid + 256 * i;  // 0..8191
        const int r = idx >> 5;         // 0..255
        const int j = idx & 31;         // 16B chunk (4 f32)
        const uint4 val = *(const uint4*)(ep + r * EP_STRIDE + j * 16);
        *(uint4*)(out + (size_t)(m0 + r) * GN + n0 + j * 4) = val;
    }
}

// ============================================================================
// Launch
// ============================================================================
extern "C" void kernel_launch(void* const* d_in, const int* in_sizes, int n_in,
                              void* d_out, int out_size) {
    (void)in_sizes; (void)n_in; (void)out_size;
    const void* p0 = d_in[0];
    const float* scale = (const float*)d_in[1];
    const void* p2 = d_in[2];
    float* out = (float*)d_out;

    probe_kernel<<<1, 32>>>((const int*)p0);
    convert_x_kernel<<<(GM * (size_t)GK) / (256 * 8), 256>>>(p0, p2);
    dequant_kernel<<<dim3(GN / 64, GK / 64), 256>>>(p0, p2, scale);

    cudaFuncSetAttribute(gemm_kernel, cudaFuncAttributeMaxDynamicSharedMemorySize, SMEM_TOTAL);
    gemm_kernel<<<dim3(GM / BM, GN / BN), 256, SMEM_TOTAL>>>(out);
}

// round 8
// speedup vs baseline: 1.2129x; 1.2129x over previous
#include <cuda_runtime.h>
#include <cuda_fp16.h>
#include <cstdint>

// ============================================================================
// Problem constants
// ============================================================================
#define GM 4096
#define GN 4096
#define GK 4096

// Scratch: dequantized weight, TRANSPOSED to [N][K] fp16 (K-major), 32 MB
__device__ __align__(1024) __half g_wt[(size_t)GN * GK];
// Scratch: x converted f32 -> fp16, [M][K], 32 MB
__device__ __align__(1024) __half g_xh[(size_t)GM * GK];

// Input-order flag: 1 if d_in[0] is q_weight (all int32 in [0,16)), 0 if it's x.
__device__ int g_order;

// ============================================================================
// Helpers
// ============================================================================
__device__ __forceinline__ uint32_t smem_u32(const void* p) {
    uint32_t a;
    asm("{ .reg .u64 t; cvta.to.shared.u64 t, %1; cvt.u32.u64 %0, t; }" : "=r"(a) : "l"(p));
    return a;
}
#define SWZ(off) ((off) ^ (((off) >> 3) & 0x70))

__device__ __forceinline__ void cp_async16(uint32_t dst, const void* src) {
    asm volatile("cp.async.cg.shared.global [%0], [%1], 16;" :: "r"(dst), "l"(src));
}
#define CP_COMMIT() asm volatile("cp.async.commit_group;" ::: "memory")
#define CP_WAIT(n)  asm volatile("cp.async.wait_group %0;" :: "n"(n) : "memory")

__device__ __forceinline__ void ldmatrix_x4(uint32_t* r, uint32_t addr) {
    asm volatile("ldmatrix.sync.aligned.m8n8.x4.shared.b16 {%0,%1,%2,%3}, [%4];"
                 : "=r"(r[0]), "=r"(r[1]), "=r"(r[2]), "=r"(r[3]) : "r"(addr));
}

__device__ __forceinline__ void mma16816(float* c, const uint32_t* a, uint32_t b0, uint32_t b1) {
    asm volatile(
        "mma.sync.aligned.m16n8k16.row.col.f32.f16.f16.f32 "
        "{%0,%1,%2,%3}, {%4,%5,%6,%7}, {%8,%9}, {%0,%1,%2,%3};"
        : "+f"(c[0]), "+f"(c[1]), "+f"(c[2]), "+f"(c[3])
        : "r"(a[0]), "r"(a[1]), "r"(a[2]), "r"(a[3]), "r"(b0), "r"(b1));
}

// ============================================================================
// Pass 0: probe which input slot holds q_weight (int32 values all in [0,16)).
// ============================================================================
__global__ void probe_kernel(const int* __restrict__ p0) {
    if (threadIdx.x == 0) {
        int ok = 1;
        for (int i = 0; i < 4096; i++) {
            unsigned v = (unsigned)p0[i];
            if (v >= 16u) { ok = 0; break; }
        }
        g_order = ok;
    }
}

// ============================================================================
// Pass 0.5: convert x (float32) -> g_xh (fp16). 8 elems/thread, vectorized.
// ============================================================================
__global__ void __launch_bounds__(256) convert_x_kernel(const void* __restrict__ p0,
                                                        const void* __restrict__ p2) {
    const float* xf = g_order ? (const float*)p2 : (const float*)p0;
    const size_t i = ((size_t)blockIdx.x * 256 + threadIdx.x) * 8;
    const float4 v0 = *(const float4*)(xf + i);
    const float4 v1 = *(const float4*)(xf + i + 4);
    union { uint2 u; __half2 h[2]; } lo, hi;
    lo.h[0] = __floats2half2_rn(v0.x, v0.y);
    lo.h[1] = __floats2half2_rn(v0.z, v0.w);
    hi.h[0] = __floats2half2_rn(v1.x, v1.y);
    hi.h[1] = __floats2half2_rn(v1.z, v1.w);
    uint4 o;
    o.x = lo.u.x; o.y = lo.u.y; o.z = hi.u.x; o.w = hi.u.y;
    *(uint4*)(&g_xh[i]) = o;
}

// ============================================================================
// Pass 1: dequant + transpose (padded smem).
// g_wt[n][k] = (half)(q[k][n] - 8) * (half)scale[k/128][n]   (scale is f32)
// ============================================================================
__global__ void __launch_bounds__(256) dequant_kernel(const void* __restrict__ p0,
                                                      const void* __restrict__ p2,
                                                      const float* __restrict__ scale) {
    const int* q = g_order ? (const int*)p0 : (const int*)p2;

    __shared__ __align__(16) __half tw[64][80];  // [n][k], padded row = 160B
    __shared__ __half sc[64];
    const int t = threadIdx.x;
    const int n0 = blockIdx.x * 64;
    const int k0 = blockIdx.y * 64;

    if (t < 64) sc[t] = __float2half_rn(scale[(size_t)(k0 >> 7) * GN + n0 + t]);
    __syncthreads();

    const int kq = t >> 4;         // 0..15 -> k rows kq*4 .. kq*4+3
    const int nq = (t & 15) << 2;  // 0..60
    const int* gp = q + (size_t)(k0 + kq * 4) * GN + n0 + nq;
    int4 v[4];
#pragma unroll
    for (int j = 0; j < 4; j++) v[j] = *(const int4*)(gp + (size_t)j * GN);

#pragma unroll
    for (int jn = 0; jn < 4; jn++) {
        const int n = nq + jn;
        const __half s = sc[n];
#pragma unroll
        for (int j = 0; j < 4; j++) {
            const int a = ((const int*)&v[j])[jn];
            tw[n][kq * 4 + j] = __hmul(__int2half_rn(a - 8), s);
        }
    }
    __syncthreads();

#pragma unroll
    for (int i = 0; i < 2; i++) {
        const int idx = t + 256 * i;   // 0..511
        const int n = idx >> 3;        // 0..63
        const int c = idx & 7;         // 16B chunk (8 halfs)
        const uint4 val = *(const uint4*)&tw[n][c * 8];
        *(uint4*)(&g_wt[(size_t)(n0 + n) * GK + k0 + c * 8]) = val;
    }
}

// ============================================================================
// Pass 2: HMMA fp16 GEMM, f32 output (rounded through fp16).
// R8: R6 shape (CTA 128x128, 8 warps, warp 32x64, BK=64, 3 stages,
// 2 CTAs/SM via launch_bounds(256,2)) + double-buffered ldmatrix fragments
// (LDSM for ks+1 overlaps MMA of ks) + ONE __syncthreads per k-tile.
// ============================================================================
#define BM 128
#define BN 128
#define BK 64
#define STAGES 3
#define KTILES (GK / BK)  // 64

#define A_BYTES (BM * 128)                 // 16 KB
#define B_BYTES (BN * 128)                 // 16 KB
#define STAGE_BYTES (A_BYTES + B_BYTES)    // 32 KB
#define SMEM_TOTAL (1024 + STAGES * STAGE_BYTES)  // 99328 B -> 2 CTAs/SM

// Epilogue staging: 128 rows x 512B padded to 528B = 67584B < SMEM_TOTAL
#define EP_STRIDE 528

__device__ __forceinline__ void load_tile(uint32_t sb, int s, int kt,
                                          int m0, int n0, int tid) {
    const uint32_t a0 = sb + s * STAGE_BYTES;
    const uint32_t b0 = a0 + A_BYTES;
    const char* ga = (const char*)(&g_xh[(size_t)m0 * GK + kt * BK]);
    const char* gb = (const char*)(&g_wt[(size_t)n0 * GK + kt * BK]);
#pragma unroll
    for (int i = 0; i < 4; i++) {  // A: 128 rows x 8 chunks = 1024 / 256 thr
        const int idx = tid + 256 * i;
        const int r = idx >> 3;
        const int c = (idx & 7) << 4;
        cp_async16(a0 + SWZ(r * 128 + c), ga + (size_t)r * (GK * 2) + c);
    }
#pragma unroll
    for (int i = 0; i < 4; i++) {  // B: 128 rows x 8 chunks
        const int idx = tid + 256 * i;
        const int r = idx >> 3;
        const int c = (idx & 7) << 4;
        cp_async16(b0 + SWZ(r * 128 + c), gb + (size_t)r * (GK * 2) + c);
    }
}

__global__ void __launch_bounds__(256, 2)
gemm_kernel(float* __restrict__ out) {
    extern __shared__ unsigned char smem_raw[];

    const uint32_t sb_raw = smem_u32(smem_raw);
    const uint32_t sb = (sb_raw + 1023u) & ~1023u;  // 1KB-aligned tile base
    unsigned char* ep = smem_raw + (sb - sb_raw);   // same region, generic ptr

    const int tid = threadIdx.x;
    const int wid = tid >> 5;
    const int lid = tid & 31;
    const int m0 = blockIdx.x * BM;
    const int n0 = blockIdx.y * BN;

    const int wm = (wid & 3) * 32;   // warp m offset
    const int wn = (wid >> 2) * 64;  // warp n offset

    float acc[2][8][4];
#pragma unroll
    for (int i = 0; i < 2; i++)
#pragma unroll
        for (int j = 0; j < 8; j++)
#pragma unroll
            for (int k = 0; k < 4; k++) acc[i][j][k] = 0.0f;

    // Prologue: fill first STAGES-1 stages
#pragma unroll
    for (int s = 0; s < STAGES - 1; s++) {
        load_tile(sb, s, s, m0, n0, tid);
        CP_COMMIT();
    }

    const int lrow = lid & 15;               // row within 16-row frag group
    const int lcol = ((lid >> 4) & 1) << 4;  // 0 or 16 bytes (k half-select)

    // Double-buffered fragments
    uint32_t afr[2][2][4], bfr[2][4][4];

    for (int kt = 0; kt < KTILES; kt++) {
        const int s = kt % STAGES;
        CP_WAIT(STAGES - 2);   // tile kt's copies (this thread's) complete
        __syncthreads();       // all threads' copies visible; prev-tile reads done

        // Prefetch tile kt+2 into the stage last read at tile kt-1 (safe after sync)
        if (kt + STAGES - 1 < KTILES)
            load_tile(sb, (kt + STAGES - 1) % STAGES, kt + STAGES - 1, m0, n0, tid);
        CP_COMMIT();  // unconditional: keeps wait_group(1) semantics at the tail

        const uint32_t abase = sb + s * STAGE_BYTES;
        const uint32_t bbase = abase + A_BYTES;

        // Preload fragments for ks=0
#pragma unroll
        for (int f = 0; f < 2; f++)
            ldmatrix_x4(afr[0][f], abase + SWZ((wm + f * 16 + lrow) * 128 + lcol));
#pragma unroll
        for (int f = 0; f < 4; f++)
            ldmatrix_x4(bfr[0][f], bbase + SWZ((wn + f * 16 + lrow) * 128 + lcol));

#pragma unroll
        for (int ks = 0; ks < BK / 16; ks++) {
            const int cur = ks & 1;
            // Prefetch fragments for ks+1 (overlaps with this step's MMAs)
            if (ks < BK / 16 - 1) {
                const int kb = (ks + 1) * 32;
#pragma unroll
                for (int f = 0; f < 2; f++)
                    ldmatrix_x4(afr[cur ^ 1][f], abase + SWZ((wm + f * 16 + lrow) * 128 + kb + lcol));
#pragma unroll
                for (int f = 0; f < 4; f++)
                    ldmatrix_x4(bfr[cur ^ 1][f], bbase + SWZ((wn + f * 16 + lrow) * 128 + kb + lcol));
            }
#pragma unroll
            for (int im = 0; im < 2; im++)
#pragma unroll
                for (int in_ = 0; in_ < 4; in_++) {
                    mma16816(acc[im][in_ * 2 + 0], afr[cur][im], bfr[cur][in_][0], bfr[cur][in_][2]);
                    mma16816(acc[im][in_ * 2 + 1], afr[cur][im], bfr[cur][in_][1], bfr[cur][in_][3]);
                }
        }
    }

    __syncthreads();  // mainloop smem reads done before epilogue overwrites

    // ------------------------------------------------------------------
    // Epilogue: round f32 -> fp16 precision, stage in padded smem,
    // coalesced 16B f32 stores.
    // ------------------------------------------------------------------
#pragma unroll
    for (int im = 0; im < 2; im++) {
        const int r_lo = wm + im * 16 + (lid >> 2);
        const int r_hi = r_lo + 8;
#pragma unroll
        for (int nf = 0; nf < 8; nf++) {
            const int n = wn + nf * 8 + 2 * (lid & 3);  // even column index
            float2 lo, hi;
            lo.x = __half2float(__float2half_rn(acc[im][nf][0]));
            lo.y = __half2float(__float2half_rn(acc[im][nf][1]));
            hi.x = __half2float(__float2half_rn(acc[im][nf][2]));
            hi.y = __half2float(__float2half_rn(acc[im][nf][3]));
            *(float2*)(ep + r_lo * EP_STRIDE + n * 4) = lo;
            *(float2*)(ep + r_hi * EP_STRIDE + n * 4) = hi;
        }
    }
    __syncthreads();

#pragma unroll
    for (int i = 0; i < 16; i++) {
        const int idx = tid + 256 * i;  // 0..4095
        const int r = idx >> 5;         // 0..127
        const int j = idx & 31;         // 16B chunk (4 f32)
        const uint4 val = *(const uint4*)(ep + r * EP_STRIDE + j * 16);
        *(uint4*)(out + (size_t)(m0 + r) * GN + n0 + j * 4) = val;
    }
}

// ============================================================================
// Launch
// ============================================================================
extern "C" void kernel_launch(void* const* d_in, const int* in_sizes, int n_in,
                              void* d_out, int out_size) {
    (void)in_sizes; (void)n_in; (void)out_size;
    const void* p0 = d_in[0];
    const float* scale = (const float*)d_in[1];
    const void* p2 = d_in[2];
    float* out = (float*)d_out;

    probe_kernel<<<1, 32>>>((const int*)p0);
    convert_x_kernel<<<(GM * (size_t)GK) / (256 * 8), 256>>>(p0, p2);
    dequant_kernel<<<dim3(GN / 64, GK / 64), 256>>>(p0, p2, scale);

    cudaFuncSetAttribute(gemm_kernel, cudaFuncAttributeMaxDynamicSharedMemorySize, SMEM_TOTAL);
    gemm_kernel<<<dim3(GM / BM, GN / BN), 256, SMEM_TOTAL>>>(out);
}